// round 11
// baseline (speedup 1.0000x reference)
#include <cuda_runtime.h>
#include <cuda_bf16.h>
#include <math.h>

#define Bn   4
#define Nn   2048
#define FIN  64
#define DOUT 128
#define ROWS (Bn*Nn)   // 8192

// ---------------- scratch (device globals; no allocation allowed) ----------
struct Scratch {
    __nv_bfloat16 q1[ROWS*DOUT], k1[ROWS*DOUT], v1[ROWS*DOUT];
    __nv_bfloat16 q2[ROWS*DOUT], k2[ROWS*DOUT], v2[ROWS*DOUT];
    __nv_bfloat16 h[ROWS*DOUT];
    float proj[ROWS*DOUT];
};
__device__ Scratch g_s;

// ---------------- helpers ----------------------------------------------------
__device__ __forceinline__ void cp16(const __nv_bfloat16* s, const __nv_bfloat16* g) {
    unsigned sa = (unsigned)__cvta_generic_to_shared((void*)s);
    asm volatile("cp.async.cg.shared.global [%0], [%1], 16;\n" :: "r"(sa), "l"(g));
}

__device__ __forceinline__ void ldsm4(unsigned* r, unsigned a) {
    asm volatile("ldmatrix.sync.aligned.m8n8.x4.shared.b16 {%0,%1,%2,%3}, [%4];\n"
        : "=r"(r[0]), "=r"(r[1]), "=r"(r[2]), "=r"(r[3]) : "r"(a));
}
__device__ __forceinline__ void ldsm4t(unsigned* r, unsigned a) {
    asm volatile("ldmatrix.sync.aligned.m8n8.x4.trans.shared.b16 {%0,%1,%2,%3}, [%4];\n"
        : "=r"(r[0]), "=r"(r[1]), "=r"(r[2]), "=r"(r[3]) : "r"(a));
}

__device__ __forceinline__ void mma_bf16(float* c, const unsigned* a,
                                         unsigned b0, unsigned b1) {
    asm volatile("mma.sync.aligned.m16n8k16.row.col.f32.bf16.bf16.f32 "
        "{%0,%1,%2,%3}, {%4,%5,%6,%7}, {%8,%9}, {%0,%1,%2,%3};\n"
        : "+f"(c[0]), "+f"(c[1]), "+f"(c[2]), "+f"(c[3])
        : "r"(a[0]), "r"(a[1]), "r"(a[2]), "r"(a[3]), "r"(b0), "r"(b1));
}

__device__ __forceinline__ unsigned pack2(float x0, float x1) {
    unsigned h;
    asm("cvt.rn.bf16x2.f32 %0, %1, %2;\n" : "=r"(h) : "f"(x1), "f"(x0));
    return h;
}

__device__ __forceinline__ float ex2(float x) {
    float y; asm("ex2.approx.ftz.f32 %0, %1;\n" : "=f"(y) : "f"(x)); return y;
}

#define GBAR(id) asm volatile("bar.sync %0, %1;" :: "r"(id), "r"(128) : "memory")

// ---------------- QKV1 + proj tensor-core GEMM --------------------------------
// C[8192,128] = x[8192,64] @ w[64,128]; blockIdx.y selects {q,k,v,proj}.
// q/k/v: single bf16 (their outputs were bf16-rounded anyway).
// proj: 3xBF16 split (xh*wh + xh*wl + xl*wh) -> ~1e-5 relative, fp32 output;
// the residual path dominates the final output so it stays near-exact.
__global__ __launch_bounds__(256) void qkv1_mma(
    const float* __restrict__ x,
    const float* __restrict__ qw, const float* __restrict__ qb,
    const float* __restrict__ kw, const float* __restrict__ kb,
    const float* __restrict__ vw, const float* __restrict__ vb,
    const float* __restrict__ pw,
    __nv_bfloat16* __restrict__ qo, __nv_bfloat16* __restrict__ ko,
    __nv_bfloat16* __restrict__ vo, float* __restrict__ po)
{
    const int y = blockIdx.y;
    const float* w    = (y==0) ? qw : (y==1) ? kw : (y==2) ? vw : pw;
    const float* bias = (y==0) ? qb : (y==1) ? kb : vb;   // unused for proj
    const bool proj = (y == 3);

    extern __shared__ __nv_bfloat16 smq[];
    __nv_bfloat16* Xh = smq;               // 128 x 72
    __nv_bfloat16* Xl = Xh + 128*72;       // 128 x 72 (proj only)
    __nv_bfloat16* Wh = Xl + 128*72;       // 64 x 136
    __nv_bfloat16* Wl = Wh + 64*136;       // 64 x 136 (proj only)

    const int tid = threadIdx.x, lane = tid & 31, warp = tid >> 5;
    const int r0 = blockIdx.x * 128;
    const int mat = lane >> 3, rin = lane & 7;

    for (int idx = tid; idx < 128*FIN; idx += 256) {
        const int r = idx >> 6, c = idx & 63;
        const float v = x[(size_t)(r0+r)*FIN + c];
        const __nv_bfloat16 hv = __float2bfloat16(v);
        Xh[r*72 + c] = hv;
        Xl[r*72 + c] = __float2bfloat16(v - __bfloat162float(hv));
    }
    for (int idx = tid; idx < FIN*128; idx += 256) {
        const int r = idx >> 7, c = idx & 127;
        const float v = w[(size_t)r*DOUT + c];
        const __nv_bfloat16 hv = __float2bfloat16(v);
        Wh[r*136 + c] = hv;
        Wl[r*136 + c] = __float2bfloat16(v - __bfloat162float(hv));
    }
    __syncthreads();

    const unsigned aX = (unsigned)__cvta_generic_to_shared(Xh)
        + (unsigned)(((warp*16 + rin + ((mat & 1) << 3)) * 72 + ((mat >> 1) << 3)) * 2);
    const unsigned aW = (unsigned)__cvta_generic_to_shared(Wh)
        + (unsigned)(((rin + ((mat & 1) << 3)) * 136 + ((mat >> 1) << 3)) * 2);
    const unsigned oXl = (unsigned)(128*72*2);
    const unsigned oWl = (unsigned)(64*136*2);

    float o[16][4];
    #pragma unroll
    for (int i = 0; i < 16; i++) { o[i][0]=0.f; o[i][1]=0.f; o[i][2]=0.f; o[i][3]=0.f; }

    #pragma unroll
    for (int kt = 0; kt < 4; kt++) {
        unsigned ah[4], al[4];
        ldsm4(ah, aX + kt*32);
        if (proj) ldsm4(al, aX + oXl + kt*32);
        #pragma unroll
        for (int np = 0; np < 8; np++) {
            const unsigned off = (unsigned)((kt*16*136 + np*16) * 2);
            unsigned bh[4];
            ldsm4t(bh, aW + off);
            mma_bf16(o[2*np],   ah, bh[0], bh[1]);
            mma_bf16(o[2*np+1], ah, bh[2], bh[3]);
            if (proj) {
                unsigned bl[4];
                ldsm4t(bl, aW + oWl + off);
                mma_bf16(o[2*np],   ah, bl[0], bl[1]);
                mma_bf16(o[2*np+1], ah, bl[2], bl[3]);
                mma_bf16(o[2*np],   al, bh[0], bh[1]);
                mma_bf16(o[2*np+1], al, bh[2], bh[3]);
            }
        }
    }

    const int rg = r0 + warp*16 + (lane >> 2);
    const int c0 = (lane & 3) * 2;
    if (proj) {
        #pragma unroll
        for (int no = 0; no < 16; no++) {
            *(float2*)&po[(size_t)rg*DOUT + no*8 + c0]     = make_float2(o[no][0], o[no][1]);
            *(float2*)&po[(size_t)(rg+8)*DOUT + no*8 + c0] = make_float2(o[no][2], o[no][3]);
        }
    } else {
        const float scale = (y==0) ? 0.17677669529663689f * 1.4426950408889634f : 1.f;
        __nv_bfloat16* outp = (y==0) ? qo : (y==1) ? ko : vo;
        #pragma unroll
        for (int no = 0; no < 16; no++) {
            const float b0 = bias[no*8 + c0], b1 = bias[no*8 + c0 + 1];
            *(unsigned*)&outp[(size_t)rg*DOUT + no*8 + c0] =
                pack2((o[no][0]+b0)*scale, (o[no][1]+b1)*scale);
            *(unsigned*)&outp[(size_t)(rg+8)*DOUT + no*8 + c0] =
                pack2((o[no][2]+b0)*scale, (o[no][3]+b1)*scale);
        }
    }
}

// ---------------- QKV2 tensor-core GEMM (bf16 h input) ------------------------
__global__ __launch_bounds__(256) void qkv2_mma(
    const __nv_bfloat16* __restrict__ hin,
    const float* __restrict__ qw, const float* __restrict__ qb,
    const float* __restrict__ kw, const float* __restrict__ kb,
    const float* __restrict__ vw, const float* __restrict__ vb,
    __nv_bfloat16* __restrict__ qo, __nv_bfloat16* __restrict__ ko,
    __nv_bfloat16* __restrict__ vo)
{
    const float* w; const float* bias; __nv_bfloat16* outp; float scale;
    if (blockIdx.y == 0)      { w = qw; bias = qb; outp = qo;
        scale = 0.08838834764831845f * 1.4426950408889634f; }   // log2e/sqrt(128)
    else if (blockIdx.y == 1) { w = kw; bias = kb; outp = ko; scale = 1.f; }
    else                      { w = vw; bias = vb; outp = vo; scale = 1.f; }

    extern __shared__ __nv_bfloat16 smq2[];
    __nv_bfloat16* Hs = smq2;              // 128 x 136
    __nv_bfloat16* Ws = Hs + 128*136;      // 128 x 136

    const int tid = threadIdx.x, lane = tid & 31, warp = tid >> 5;
    const int r0 = blockIdx.x * 128;
    const int mat = lane >> 3, rin = lane & 7;

    for (int idx = tid; idx < 128*16; idx += 256) {
        const int r = idx >> 4, c = (idx & 15) * 8;
        cp16(Hs + r*136 + c, hin + (size_t)(r0+r)*DOUT + c);
    }
    asm volatile("cp.async.commit_group;\n" ::: "memory");
    for (int idx = tid; idx < 128*128; idx += 256) {
        const int r = idx >> 7, c = idx & 127;
        Ws[r*136 + c] = __float2bfloat16(w[(size_t)r*DOUT + c]);
    }
    asm volatile("cp.async.wait_group 0;\n" ::: "memory");
    __syncthreads();

    const unsigned aH = (unsigned)__cvta_generic_to_shared(Hs)
        + (unsigned)(((warp*16 + rin + ((mat & 1) << 3)) * 136 + ((mat >> 1) << 3)) * 2);
    const unsigned aW = (unsigned)__cvta_generic_to_shared(Ws)
        + (unsigned)(((rin + ((mat & 1) << 3)) * 136 + ((mat >> 1) << 3)) * 2);

    float o[16][4];
    #pragma unroll
    for (int i = 0; i < 16; i++) { o[i][0]=0.f; o[i][1]=0.f; o[i][2]=0.f; o[i][3]=0.f; }

    #pragma unroll
    for (int kt = 0; kt < 8; kt++) {
        unsigned a4[4];
        ldsm4(a4, aH + kt*32);
        #pragma unroll
        for (int np = 0; np < 8; np++) {
            unsigned b4[4];
            ldsm4t(b4, aW + (unsigned)((kt*16*136 + np*16) * 2));
            mma_bf16(o[2*np],   a4, b4[0], b4[1]);
            mma_bf16(o[2*np+1], a4, b4[2], b4[3]);
        }
    }

    const int rg = r0 + warp*16 + (lane >> 2);
    const int c0 = (lane & 3) * 2;
    #pragma unroll
    for (int no = 0; no < 16; no++) {
        const float b0 = bias[no*8 + c0], b1 = bias[no*8 + c0 + 1];
        *(unsigned*)&outp[(size_t)rg*DOUT + no*8 + c0] =
            pack2((o[no][0]+b0)*scale, (o[no][1]+b1)*scale);
        *(unsigned*)&outp[(size_t)(rg+8)*DOUT + no*8 + c0] =
            pack2((o[no][2]+b0)*scale, (o[no][3]+b1)*scale);
    }
}

// ---------------- GAT1: 4 heads merged in one CTA (block-diagonal S) ----------
__global__ __launch_bounds__(512, 1) void attn1_4h(
    const __nv_bfloat16* __restrict__ Qg, const __nv_bfloat16* __restrict__ Kgm,
    const __nv_bfloat16* __restrict__ Vgm, __nv_bfloat16* __restrict__ Og)
{
    constexpr int D = 128, BQ = 64, BK = 32, DP = D + 8;
    constexpr int QT = BQ * DP, KT = BK * DP;
    constexpr int NG = 4, TTG = Nn / BK / NG;   // 16

    extern __shared__ char smraw[];
    __nv_bfloat16* sm  = (__nv_bfloat16*)smraw;
    __nv_bfloat16* Qhs = sm;

    const int tid = threadIdx.x, lane = tid & 31, warp = tid >> 5;
    const int grp = warp >> 2, wg = warp & 3, gtid = tid & 127;
    const size_t base = (size_t)blockIdx.y * Nn * DOUT;
    const int q0 = blockIdx.x * BQ;

    __nv_bfloat16* Kg = sm + QT + grp*4*KT;

    for (int idx = tid; idx < BQ*(D/8); idx += 512) {
        const int r = idx / (D/8), c = (idx % (D/8)) * 8;
        cp16(Qhs + r*DP + c, Qg + base + (size_t)(q0 + r) * DOUT + c);
    }
    asm volatile("cp.async.commit_group;\n" ::: "memory");

    auto stage = [&](int buf, int tt) {
        const int k0 = (NG*tt + grp) * BK;
        for (int idx = gtid; idx < BK*(D/8); idx += 128) {
            const int r = idx / (D/8), c = (idx % (D/8)) * 8;
            const size_t go = base + (size_t)(k0 + r) * DOUT + c;
            const int s = buf*KT + r*DP + c;
            cp16(Kg + s,        Kgm + go);
            cp16(Kg + 2*KT + s, Vgm + go);
        }
        asm volatile("cp.async.commit_group;\n" ::: "memory");
    };
    stage(0, 0);
    stage(1, 1);
    asm volatile("cp.async.wait_group 2;\n" ::: "memory");
    __syncthreads();

    const int mat = lane >> 3, rin = lane & 7;
    const unsigned sbase = (unsigned)__cvta_generic_to_shared(sm);
    const unsigned aQ = sbase
        + (unsigned)(((wg*16 + rin + ((mat & 1) << 3)) * DP + ((mat >> 1) << 3)) * 2);
    const unsigned kgb = sbase + (unsigned)((QT + grp*4*KT) * 2);
    const unsigned aK = kgb
        + (unsigned)(((rin + ((mat >> 1) << 3)) * DP + ((mat & 1) << 3)) * 2);
    const unsigned aV = kgb + (unsigned)(2*KT*2)
        + (unsigned)(((rin + ((mat & 1) << 3)) * DP + ((mat >> 1) << 3)) * 2);

    float o[16][4];
    #pragma unroll
    for (int i = 0; i < 16; i++) { o[i][0]=0.f; o[i][1]=0.f; o[i][2]=0.f; o[i][3]=0.f; }
    float ls0[4] = {0.f,0.f,0.f,0.f}, ls1[4] = {0.f,0.f,0.f,0.f};

    for (int tt = 0; tt < TTG; tt++) {
        if (tt == TTG-1) asm volatile("cp.async.wait_group 0;\n" ::: "memory");
        else             asm volatile("cp.async.wait_group 1;\n" ::: "memory");
        GBAR(1 + grp);
        const unsigned kb = (unsigned)((tt & 1) * KT * 2);

        #pragma unroll
        for (int hh = 0; hh < 4; hh++) {
            float sc[4][4];
            #pragma unroll
            for (int i = 0; i < 4; i++) { sc[i][0]=0.f; sc[i][1]=0.f; sc[i][2]=0.f; sc[i][3]=0.f; }
            #pragma unroll
            for (int k2 = 0; k2 < 2; k2++) {
                const int kt = 2*hh + k2;
                unsigned qa[4];
                ldsm4(qa, aQ + kt*32);
                unsigned bh[2][4];
                #pragma unroll
                for (int np = 0; np < 2; np++)
                    ldsm4(bh[np], aK + kb + (unsigned)((np*16*DP + kt*16) * 2));
                #pragma unroll
                for (int np = 0; np < 2; np++) {
                    mma_bf16(sc[2*np],   qa, bh[np][0], bh[np][1]);
                    mma_bf16(sc[2*np+1], qa, bh[np][2], bh[np][3]);
                }
            }
            #pragma unroll
            for (int nt = 0; nt < 4; nt++) {
                sc[nt][0] = ex2(sc[nt][0]);
                sc[nt][1] = ex2(sc[nt][1]);
                sc[nt][2] = ex2(sc[nt][2]);
                sc[nt][3] = ex2(sc[nt][3]);
                ls0[hh] += sc[nt][0] + sc[nt][1];
                ls1[hh] += sc[nt][2] + sc[nt][3];
            }
            #pragma unroll
            for (int kt2 = 0; kt2 < 2; kt2++) {
                unsigned pa[4];
                pa[0] = pack2(sc[2*kt2][0],   sc[2*kt2][1]);
                pa[1] = pack2(sc[2*kt2][2],   sc[2*kt2][3]);
                pa[2] = pack2(sc[2*kt2+1][0], sc[2*kt2+1][1]);
                pa[3] = pack2(sc[2*kt2+1][2], sc[2*kt2+1][3]);
                #pragma unroll
                for (int j = 0; j < 2; j++) {
                    const int np = 2*hh + j;
                    unsigned vh[4];
                    ldsm4t(vh, aV + kb + (unsigned)((kt2*16*DP + np*16) * 2));
                    mma_bf16(o[2*np],   pa, vh[0], vh[1]);
                    mma_bf16(o[2*np+1], pa, vh[2], vh[3]);
                }
            }
        }
        GBAR(1 + grp);
        if (tt + 2 < TTG) stage(tt & 1, tt + 2);
    }

    #pragma unroll
    for (int hh = 0; hh < 4; hh++) {
        ls0[hh] += __shfl_xor_sync(0xffffffffu, ls0[hh], 1);
        ls0[hh] += __shfl_xor_sync(0xffffffffu, ls0[hh], 2);
        ls1[hh] += __shfl_xor_sync(0xffffffffu, ls1[hh], 1);
        ls1[hh] += __shfl_xor_sync(0xffffffffu, ls1[hh], 2);
    }

    __syncthreads();
    float* mb = (float*)smraw;
    constexpr int MW = 8 + 64;
    if (grp > 0) {
        float* p = mb + ((grp-1)*128 + gtid)*MW;
        #pragma unroll
        for (int hh = 0; hh < 4; hh++) { p[hh] = ls0[hh]; p[4+hh] = ls1[hh]; }
        #pragma unroll
        for (int no = 0; no < 16; no++) {
            p[8+no*4+0] = o[no][0]; p[8+no*4+1] = o[no][1];
            p[8+no*4+2] = o[no][2]; p[8+no*4+3] = o[no][3];
        }
    }
    __syncthreads();
    if (grp == 0) {
        #pragma unroll
        for (int g2 = 0; g2 < NG-1; g2++) {
            const float* p = mb + (g2*128 + gtid)*MW;
            #pragma unroll
            for (int hh = 0; hh < 4; hh++) { ls0[hh] += p[hh]; ls1[hh] += p[4+hh]; }
            #pragma unroll
            for (int no = 0; no < 16; no++) {
                o[no][0] += p[8+no*4+0]; o[no][1] += p[8+no*4+1];
                o[no][2] += p[8+no*4+2]; o[no][3] += p[8+no*4+3];
            }
        }
        float i0[4], i1[4];
        #pragma unroll
        for (int hh = 0; hh < 4; hh++) { i0[hh] = 1.f/ls0[hh]; i1[hh] = 1.f/ls1[hh]; }
        const int rg = q0 + wg*16 + (lane >> 2);
        const int c0 = (lane & 3) * 2;
        #pragma unroll
        for (int no = 0; no < 16; no++) {
            const int hh = no >> 2;
            float v0 = fmaxf(o[no][0] * i0[hh], 0.f);
            float v1 = fmaxf(o[no][1] * i0[hh], 0.f);
            float v2 = fmaxf(o[no][2] * i1[hh], 0.f);
            float v3 = fmaxf(o[no][3] * i1[hh], 0.f);
            *(unsigned*)&Og[base + (size_t)rg*DOUT + no*8 + c0]     = pack2(v0, v1);
            *(unsigned*)&Og[base + (size_t)(rg+8)*DOUT + no*8 + c0] = pack2(v2, v3);
        }
    }
}

// ---------------- GAT2 attention + smem-staged residual add + LayerNorm -------
// LN fusion v2: grp 0 writes the NORMALIZED attention rows into a smem staging
// buffer (o registers die there), then ALL 16 warps run a lightweight LN phase
// (y = stage + proj; two warp reductions; write d_out). Avoids the round-8
// register blowup because no thread holds o while doing LN.
__global__ __launch_bounds__(512, 1) void attn2_mma(
    const __nv_bfloat16* __restrict__ Qg, const __nv_bfloat16* __restrict__ Kgm,
    const __nv_bfloat16* __restrict__ Vgm,
    const float* __restrict__ projg, const float* __restrict__ lng,
    const float* __restrict__ lnb, float* __restrict__ Og)
{
    constexpr int D = 128, BQ = 64, BK = 32, DP = D + 8;
    constexpr int NKT = D / 16, NPS = BK / 16, NT = BK / 8, NO = D / 8, NPV = D / 16;
    constexpr int QT = BQ * DP, KT = BK * DP;
    constexpr int NG = 4, TTG = Nn / BK / NG;

    extern __shared__ char smraw[];
    __nv_bfloat16* sm  = (__nv_bfloat16*)smraw;
    __nv_bfloat16* Qhs = sm;

    const int tid = threadIdx.x, lane = tid & 31, warp = tid >> 5;
    const int grp = warp >> 2, wg = warp & 3, gtid = tid & 127;
    const size_t base = (size_t)blockIdx.y * Nn * DOUT;
    const int q0 = blockIdx.x * BQ;

    __nv_bfloat16* Kg = sm + QT + grp*4*KT;

    for (int idx = tid; idx < BQ*(D/8); idx += 512) {
        const int r = idx / (D/8), c = (idx % (D/8)) * 8;
        cp16(Qhs + r*DP + c, Qg + base + (size_t)(q0 + r) * DOUT + c);
    }
    asm volatile("cp.async.commit_group;\n" ::: "memory");

    auto stage = [&](int buf, int tt) {
        const int k0 = (NG*tt + grp) * BK;
        for (int idx = gtid; idx < BK*(D/8); idx += 128) {
            const int r = idx / (D/8), c = (idx % (D/8)) * 8;
            const size_t go = base + (size_t)(k0 + r) * DOUT + c;
            const int s = buf*KT + r*DP + c;
            cp16(Kg + s,        Kgm + go);
            cp16(Kg + 2*KT + s, Vgm + go);
        }
        asm volatile("cp.async.commit_group;\n" ::: "memory");
    };
    stage(0, 0);
    stage(1, 1);
    asm volatile("cp.async.wait_group 2;\n" ::: "memory");
    __syncthreads();

    const int mat = lane >> 3, rin = lane & 7;
    const unsigned sbase = (unsigned)__cvta_generic_to_shared(sm);
    const unsigned aQ = sbase
        + (unsigned)(((wg*16 + rin + ((mat & 1) << 3)) * DP + ((mat >> 1) << 3)) * 2);
    const unsigned kgb = sbase + (unsigned)((QT + grp*4*KT) * 2);
    const unsigned aK = kgb
        + (unsigned)(((rin + ((mat >> 1) << 3)) * DP + ((mat & 1) << 3)) * 2);
    const unsigned aV = kgb + (unsigned)(2*KT*2)
        + (unsigned)(((rin + ((mat & 1) << 3)) * DP + ((mat >> 1) << 3)) * 2);

    float o[NO][4];
    #pragma unroll
    for (int i = 0; i < NO; i++) { o[i][0]=0.f; o[i][1]=0.f; o[i][2]=0.f; o[i][3]=0.f; }
    float ls0 = 0.f, ls1 = 0.f;

    for (int tt = 0; tt < TTG; tt++) {
        if (tt == TTG-1) asm volatile("cp.async.wait_group 0;\n" ::: "memory");
        else             asm volatile("cp.async.wait_group 1;\n" ::: "memory");
        GBAR(1 + grp);
        const unsigned kb = (unsigned)((tt & 1) * KT * 2);

        float sc[NT][4];
        #pragma unroll
        for (int i = 0; i < NT; i++) { sc[i][0]=0.f; sc[i][1]=0.f; sc[i][2]=0.f; sc[i][3]=0.f; }

        #pragma unroll
        for (int kt = 0; kt < NKT; kt++) {
            unsigned qa[4];
            ldsm4(qa, aQ + kt*32);
            unsigned bh[NPS][4];
            #pragma unroll
            for (int np = 0; np < NPS; np++)
                ldsm4(bh[np], aK + kb + (unsigned)((np*16*DP + kt*16) * 2));
            #pragma unroll
            for (int np = 0; np < NPS; np++) {
                mma_bf16(sc[2*np],   qa, bh[np][0], bh[np][1]);
                mma_bf16(sc[2*np+1], qa, bh[np][2], bh[np][3]);
            }
        }

        #pragma unroll
        for (int nt = 0; nt < NT; nt++) {
            sc[nt][0] = ex2(sc[nt][0]);
            sc[nt][1] = ex2(sc[nt][1]);
            sc[nt][2] = ex2(sc[nt][2]);
            sc[nt][3] = ex2(sc[nt][3]);
            ls0 += sc[nt][0] + sc[nt][1];
            ls1 += sc[nt][2] + sc[nt][3];
        }

        #pragma unroll
        for (int kt2 = 0; kt2 < NPS; kt2++) {
            unsigned pa[4];
            pa[0] = pack2(sc[2*kt2][0],   sc[2*kt2][1]);
            pa[1] = pack2(sc[2*kt2][2],   sc[2*kt2][3]);
            pa[2] = pack2(sc[2*kt2+1][0], sc[2*kt2+1][1]);
            pa[3] = pack2(sc[2*kt2+1][2], sc[2*kt2+1][3]);
            #pragma unroll
            for (int np = 0; np < NPV; np++) {
                unsigned vh[4];
                ldsm4t(vh, aV + kb + (unsigned)((kt2*16*DP + np*16) * 2));
                mma_bf16(o[2*np],   pa, vh[0], vh[1]);
                mma_bf16(o[2*np+1], pa, vh[2], vh[3]);
            }
        }
        GBAR(1 + grp);
        if (tt + 2 < TTG) stage(tt & 1, tt + 2);
    }

    ls0 += __shfl_xor_sync(0xffffffffu, ls0, 1);
    ls0 += __shfl_xor_sync(0xffffffffu, ls0, 2);
    ls1 += __shfl_xor_sync(0xffffffffu, ls1, 1);
    ls1 += __shfl_xor_sync(0xffffffffu, ls1, 2);

    // ---- merge the four group partials in smem, grp 0 normalizes to ybuf ----
    __syncthreads();
    float* mb = (float*)smraw;
    constexpr int MW = 2 + NO*4;                 // 66
    float* ybuf = mb + 3*128*MW;                 // 64 x 128 fp32 staging (32 KB)
    if (grp > 0) {
        float* p = mb + ((grp-1)*128 + gtid)*MW;
        p[0] = ls0; p[1] = ls1;
        #pragma unroll
        for (int no = 0; no < NO; no++) {
            p[2+no*4+0] = o[no][0]; p[2+no*4+1] = o[no][1];
            p[2+no*4+2] = o[no][2]; p[2+no*4+3] = o[no][3];
        }
    }
    __syncthreads();
    if (grp == 0) {
        #pragma unroll
        for (int g2 = 0; g2 < NG-1; g2++) {
            const float* p = mb + (g2*128 + gtid)*MW;
            ls0 += p[0]; ls1 += p[1];
            #pragma unroll
            for (int no = 0; no < NO; no++) {
                o[no][0] += p[2+no*4+0]; o[no][1] += p[2+no*4+1];
                o[no][2] += p[2+no*4+2]; o[no][3] += p[2+no*4+3];
            }
        }
        const float i0 = 1.f / ls0, i1 = 1.f / ls1;
        const int rl = wg*16 + (lane >> 2);      // local row 0..63
        const int c0 = (lane & 3) * 2;
        #pragma unroll
        for (int no = 0; no < NO; no++) {
            *(float2*)&ybuf[rl*DOUT + no*8 + c0] =
                make_float2(o[no][0]*i0, o[no][1]*i0);
            *(float2*)&ybuf[(rl+8)*DOUT + no*8 + c0] =
                make_float2(o[no][2]*i1, o[no][3]*i1);
        }
    }
    __syncthreads();

    // ---- LN phase: all 16 warps, 4 rows each, lane owns 4 cols (float4) ----
    #pragma unroll
    for (int r = 0; r < 4; r++) {
        const int rr = warp*4 + r;               // local row 0..63
        float4 y4 = *(float4*)&ybuf[rr*DOUT + lane*4];
        const float4 p4 = *(const float4*)&projg[base + (size_t)(q0+rr)*DOUT + lane*4];
        y4.x += p4.x; y4.y += p4.y; y4.z += p4.z; y4.w += p4.w;
        float s  = y4.x + y4.y + y4.z + y4.w;
        float s2 = y4.x*y4.x + y4.y*y4.y + y4.z*y4.z + y4.w*y4.w;
        #pragma unroll
        for (int off = 16; off > 0; off >>= 1) {
            s  += __shfl_xor_sync(0xffffffffu, s,  off);
            s2 += __shfl_xor_sync(0xffffffffu, s2, off);
        }
        const float mu = s * (1.f/128.f);
        const float rv = rsqrtf(s2*(1.f/128.f) - mu*mu + 1e-3f);
        const float4 g4 = *(const float4*)&lng[lane*4];
        const float4 b4 = *(const float4*)&lnb[lane*4];
        float4 out4;
        out4.x = (y4.x - mu)*rv*g4.x + b4.x;
        out4.y = (y4.y - mu)*rv*g4.y + b4.y;
        out4.z = (y4.z - mu)*rv*g4.z + b4.z;
        out4.w = (y4.w - mu)*rv*g4.w + b4.w;
        *(float4*)&Og[base + (size_t)(q0+rr)*DOUT + lane*4] = out4;
    }
}

// ---------------- launch -------------------------------------------------------
extern "C" void kernel_launch(void* const* d_in, const int* in_sizes, int n_in,
                              void* d_out, int out_size)
{
    (void)in_sizes; (void)n_in; (void)out_size;
    const float* x   = (const float*)d_in[0];
    // d_in[1] = emb : unused (adjacency mask is a provable no-op)
    const float* q1w = (const float*)d_in[2];
    const float* q1b = (const float*)d_in[3];
    const float* k1w = (const float*)d_in[4];
    const float* k1b = (const float*)d_in[5];
    const float* v1w = (const float*)d_in[6];
    const float* v1b = (const float*)d_in[7];
    const float* q2w = (const float*)d_in[8];
    const float* q2b = (const float*)d_in[9];
    const float* k2w = (const float*)d_in[10];
    const float* k2b = (const float*)d_in[11];
    const float* v2w = (const float*)d_in[12];
    const float* v2b = (const float*)d_in[13];
    const float* pw  = (const float*)d_in[14];
    const float* lng = (const float*)d_in[15];
    const float* lnb = (const float*)d_in[16];
    float* out = (float*)d_out;

    Scratch* sp = nullptr;
    cudaGetSymbolAddress((void**)&sp, g_s);

    const int SMEM_A  = (64*136 + 16*32*136) * 2;            // 156672 B (attn)
    const int SMEM_Q1 = (2*128*72 + 2*64*136) * 2;           //  71680 B
    const int SMEM_Q2 = (2*128*136) * 2;                     //  69632 B
    cudaFuncSetAttribute(attn1_4h,
                         cudaFuncAttributeMaxDynamicSharedMemorySize, SMEM_A);
    cudaFuncSetAttribute(attn2_mma,
                         cudaFuncAttributeMaxDynamicSharedMemorySize, SMEM_A);
    cudaFuncSetAttribute(qkv1_mma,
                         cudaFuncAttributeMaxDynamicSharedMemorySize, SMEM_Q1);
    cudaFuncSetAttribute(qkv2_mma,
                         cudaFuncAttributeMaxDynamicSharedMemorySize, SMEM_Q2);

    qkv1_mma<<<dim3(ROWS/128, 4), 256, SMEM_Q1>>>(x, q1w,q1b, k1w,k1b, v1w,v1b,
        pw, sp->q1, sp->k1, sp->v1, sp->proj);

    attn1_4h<<<dim3(Nn/64, Bn), 512, SMEM_A>>>(sp->q1, sp->k1, sp->v1, sp->h);

    qkv2_mma<<<dim3(ROWS/128, 3), 256, SMEM_Q2>>>(sp->h, q2w,q2b, k2w,k2b,
        v2w,v2b, sp->q2, sp->k2, sp->v2);

    attn2_mma<<<dim3(Nn/64, Bn), 512, SMEM_A>>>(sp->q2, sp->k2, sp->v2,
        sp->proj, lng, lnb, out);
}

// round 12
// speedup vs baseline: 1.5267x; 1.5267x over previous
#include <cuda_runtime.h>
#include <cuda_bf16.h>
#include <math.h>

#define Bn   4
#define Nn   2048
#define FIN  64
#define DOUT 128
#define ROWS (Bn*Nn)   // 8192

// ---------------- scratch (device globals; no allocation allowed) ----------
struct Scratch {
    __nv_bfloat16 q1[ROWS*DOUT], k1[ROWS*DOUT], v1[ROWS*DOUT];
    __nv_bfloat16 q2[ROWS*DOUT], k2[ROWS*DOUT], v2[ROWS*DOUT];
    __nv_bfloat16 h[ROWS*DOUT];
    float proj[ROWS*DOUT];
};
__device__ Scratch g_s;

// ---------------- helpers ----------------------------------------------------
__device__ __forceinline__ void cp16(const __nv_bfloat16* s, const __nv_bfloat16* g) {
    unsigned sa = (unsigned)__cvta_generic_to_shared((void*)s);
    asm volatile("cp.async.cg.shared.global [%0], [%1], 16;\n" :: "r"(sa), "l"(g));
}

__device__ __forceinline__ void ldsm4(unsigned* r, unsigned a) {
    asm volatile("ldmatrix.sync.aligned.m8n8.x4.shared.b16 {%0,%1,%2,%3}, [%4];\n"
        : "=r"(r[0]), "=r"(r[1]), "=r"(r[2]), "=r"(r[3]) : "r"(a));
}
__device__ __forceinline__ void ldsm4t(unsigned* r, unsigned a) {
    asm volatile("ldmatrix.sync.aligned.m8n8.x4.trans.shared.b16 {%0,%1,%2,%3}, [%4];\n"
        : "=r"(r[0]), "=r"(r[1]), "=r"(r[2]), "=r"(r[3]) : "r"(a));
}

__device__ __forceinline__ void mma_bf16(float* c, const unsigned* a,
                                         unsigned b0, unsigned b1) {
    asm volatile("mma.sync.aligned.m16n8k16.row.col.f32.bf16.bf16.f32 "
        "{%0,%1,%2,%3}, {%4,%5,%6,%7}, {%8,%9}, {%0,%1,%2,%3};\n"
        : "+f"(c[0]), "+f"(c[1]), "+f"(c[2]), "+f"(c[3])
        : "r"(a[0]), "r"(a[1]), "r"(a[2]), "r"(a[3]), "r"(b0), "r"(b1));
}

__device__ __forceinline__ unsigned pack2(float x0, float x1) {
    unsigned h;
    asm("cvt.rn.bf16x2.f32 %0, %1, %2;\n" : "=r"(h) : "f"(x1), "f"(x0));
    return h;
}

__device__ __forceinline__ float ex2(float x) {
    float y; asm("ex2.approx.ftz.f32 %0, %1;\n" : "=f"(y) : "f"(x)); return y;
}

#define GBAR(id) asm volatile("bar.sync %0, %1;" :: "r"(id), "r"(128) : "memory")

// ---------------- QKV1 + proj tensor-core GEMM --------------------------------
// C[8192,128] = x[8192,64] @ w[64,128]; blockIdx.y selects {q,k,v,proj}.
// q/k/v: single bf16 (their outputs were bf16-rounded anyway).
// proj: 3xBF16 split (xh*wh + xh*wl + xl*wh) -> ~1e-5 relative, fp32 output;
// the residual path dominates the final output so it stays near-exact.
__global__ __launch_bounds__(256) void qkv1_mma(
    const float* __restrict__ x,
    const float* __restrict__ qw, const float* __restrict__ qb,
    const float* __restrict__ kw, const float* __restrict__ kb,
    const float* __restrict__ vw, const float* __restrict__ vb,
    const float* __restrict__ pw,
    __nv_bfloat16* __restrict__ qo, __nv_bfloat16* __restrict__ ko,
    __nv_bfloat16* __restrict__ vo, float* __restrict__ po)
{
    const int y = blockIdx.y;
    const float* w    = (y==0) ? qw : (y==1) ? kw : (y==2) ? vw : pw;
    const float* bias = (y==0) ? qb : (y==1) ? kb : vb;   // unused for proj
    const bool proj = (y == 3);

    extern __shared__ __nv_bfloat16 smq[];
    __nv_bfloat16* Xh = smq;               // 128 x 72
    __nv_bfloat16* Xl = Xh + 128*72;       // 128 x 72 (proj only)
    __nv_bfloat16* Wh = Xl + 128*72;       // 64 x 136
    __nv_bfloat16* Wl = Wh + 64*136;       // 64 x 136 (proj only)

    const int tid = threadIdx.x, lane = tid & 31, warp = tid >> 5;
    const int r0 = blockIdx.x * 128;
    const int mat = lane >> 3, rin = lane & 7;

    for (int idx = tid; idx < 128*FIN; idx += 256) {
        const int r = idx >> 6, c = idx & 63;
        const float v = x[(size_t)(r0+r)*FIN + c];
        const __nv_bfloat16 hv = __float2bfloat16(v);
        Xh[r*72 + c] = hv;
        Xl[r*72 + c] = __float2bfloat16(v - __bfloat162float(hv));
    }
    for (int idx = tid; idx < FIN*128; idx += 256) {
        const int r = idx >> 7, c = idx & 127;
        const float v = w[(size_t)r*DOUT + c];
        const __nv_bfloat16 hv = __float2bfloat16(v);
        Wh[r*136 + c] = hv;
        Wl[r*136 + c] = __float2bfloat16(v - __bfloat162float(hv));
    }
    __syncthreads();

    const unsigned aX = (unsigned)__cvta_generic_to_shared(Xh)
        + (unsigned)(((warp*16 + rin + ((mat & 1) << 3)) * 72 + ((mat >> 1) << 3)) * 2);
    const unsigned aW = (unsigned)__cvta_generic_to_shared(Wh)
        + (unsigned)(((rin + ((mat & 1) << 3)) * 136 + ((mat >> 1) << 3)) * 2);
    const unsigned oXl = (unsigned)(128*72*2);
    const unsigned oWl = (unsigned)(64*136*2);

    float o[16][4];
    #pragma unroll
    for (int i = 0; i < 16; i++) { o[i][0]=0.f; o[i][1]=0.f; o[i][2]=0.f; o[i][3]=0.f; }

    #pragma unroll
    for (int kt = 0; kt < 4; kt++) {
        unsigned ah[4], al[4];
        ldsm4(ah, aX + kt*32);
        if (proj) ldsm4(al, aX + oXl + kt*32);
        #pragma unroll
        for (int np = 0; np < 8; np++) {
            const unsigned off = (unsigned)((kt*16*136 + np*16) * 2);
            unsigned bh[4];
            ldsm4t(bh, aW + off);
            mma_bf16(o[2*np],   ah, bh[0], bh[1]);
            mma_bf16(o[2*np+1], ah, bh[2], bh[3]);
            if (proj) {
                unsigned bl[4];
                ldsm4t(bl, aW + oWl + off);
                mma_bf16(o[2*np],   ah, bl[0], bl[1]);
                mma_bf16(o[2*np+1], ah, bl[2], bl[3]);
                mma_bf16(o[2*np],   al, bh[0], bh[1]);
                mma_bf16(o[2*np+1], al, bh[2], bh[3]);
            }
        }
    }

    const int rg = r0 + warp*16 + (lane >> 2);
    const int c0 = (lane & 3) * 2;
    if (proj) {
        #pragma unroll
        for (int no = 0; no < 16; no++) {
            *(float2*)&po[(size_t)rg*DOUT + no*8 + c0]     = make_float2(o[no][0], o[no][1]);
            *(float2*)&po[(size_t)(rg+8)*DOUT + no*8 + c0] = make_float2(o[no][2], o[no][3]);
        }
    } else {
        const float scale = (y==0) ? 0.17677669529663689f * 1.4426950408889634f : 1.f;
        __nv_bfloat16* outp = (y==0) ? qo : (y==1) ? ko : vo;
        #pragma unroll
        for (int no = 0; no < 16; no++) {
            const float b0 = bias[no*8 + c0], b1 = bias[no*8 + c0 + 1];
            *(unsigned*)&outp[(size_t)rg*DOUT + no*8 + c0] =
                pack2((o[no][0]+b0)*scale, (o[no][1]+b1)*scale);
            *(unsigned*)&outp[(size_t)(rg+8)*DOUT + no*8 + c0] =
                pack2((o[no][2]+b0)*scale, (o[no][3]+b1)*scale);
        }
    }
}

// ---------------- QKV2 tensor-core GEMM (bf16 h input) ------------------------
__global__ __launch_bounds__(256) void qkv2_mma(
    const __nv_bfloat16* __restrict__ hin,
    const float* __restrict__ qw, const float* __restrict__ qb,
    const float* __restrict__ kw, const float* __restrict__ kb,
    const float* __restrict__ vw, const float* __restrict__ vb,
    __nv_bfloat16* __restrict__ qo, __nv_bfloat16* __restrict__ ko,
    __nv_bfloat16* __restrict__ vo)
{
    const float* w; const float* bias; __nv_bfloat16* outp; float scale;
    if (blockIdx.y == 0)      { w = qw; bias = qb; outp = qo;
        scale = 0.08838834764831845f * 1.4426950408889634f; }   // log2e/sqrt(128)
    else if (blockIdx.y == 1) { w = kw; bias = kb; outp = ko; scale = 1.f; }
    else                      { w = vw; bias = vb; outp = vo; scale = 1.f; }

    extern __shared__ __nv_bfloat16 smq2[];
    __nv_bfloat16* Hs = smq2;              // 128 x 136
    __nv_bfloat16* Ws = Hs + 128*136;      // 128 x 136

    const int tid = threadIdx.x, lane = tid & 31, warp = tid >> 5;
    const int r0 = blockIdx.x * 128;
    const int mat = lane >> 3, rin = lane & 7;

    for (int idx = tid; idx < 128*16; idx += 256) {
        const int r = idx >> 4, c = (idx & 15) * 8;
        cp16(Hs + r*136 + c, hin + (size_t)(r0+r)*DOUT + c);
    }
    asm volatile("cp.async.commit_group;\n" ::: "memory");
    for (int idx = tid; idx < 128*128; idx += 256) {
        const int r = idx >> 7, c = idx & 127;
        Ws[r*136 + c] = __float2bfloat16(w[(size_t)r*DOUT + c]);
    }
    asm volatile("cp.async.wait_group 0;\n" ::: "memory");
    __syncthreads();

    const unsigned aH = (unsigned)__cvta_generic_to_shared(Hs)
        + (unsigned)(((warp*16 + rin + ((mat & 1) << 3)) * 136 + ((mat >> 1) << 3)) * 2);
    const unsigned aW = (unsigned)__cvta_generic_to_shared(Ws)
        + (unsigned)(((rin + ((mat & 1) << 3)) * 136 + ((mat >> 1) << 3)) * 2);

    float o[16][4];
    #pragma unroll
    for (int i = 0; i < 16; i++) { o[i][0]=0.f; o[i][1]=0.f; o[i][2]=0.f; o[i][3]=0.f; }

    #pragma unroll
    for (int kt = 0; kt < 8; kt++) {
        unsigned a4[4];
        ldsm4(a4, aH + kt*32);
        #pragma unroll
        for (int np = 0; np < 8; np++) {
            unsigned b4[4];
            ldsm4t(b4, aW + (unsigned)((kt*16*136 + np*16) * 2));
            mma_bf16(o[2*np],   a4, b4[0], b4[1]);
            mma_bf16(o[2*np+1], a4, b4[2], b4[3]);
        }
    }

    const int rg = r0 + warp*16 + (lane >> 2);
    const int c0 = (lane & 3) * 2;
    #pragma unroll
    for (int no = 0; no < 16; no++) {
        const float b0 = bias[no*8 + c0], b1 = bias[no*8 + c0 + 1];
        *(unsigned*)&outp[(size_t)rg*DOUT + no*8 + c0] =
            pack2((o[no][0]+b0)*scale, (o[no][1]+b1)*scale);
        *(unsigned*)&outp[(size_t)(rg+8)*DOUT + no*8 + c0] =
            pack2((o[no][2]+b0)*scale, (o[no][3]+b1)*scale);
    }
}

// ---------------- GAT1: 4 heads merged in one CTA (block-diagonal S) ----------
__global__ __launch_bounds__(512, 1) void attn1_4h(
    const __nv_bfloat16* __restrict__ Qg, const __nv_bfloat16* __restrict__ Kgm,
    const __nv_bfloat16* __restrict__ Vgm, __nv_bfloat16* __restrict__ Og)
{
    constexpr int D = 128, BQ = 64, BK = 32, DP = D + 8;
    constexpr int QT = BQ * DP, KT = BK * DP;
    constexpr int NG = 4, TTG = Nn / BK / NG;   // 16

    extern __shared__ char smraw[];
    __nv_bfloat16* sm  = (__nv_bfloat16*)smraw;
    __nv_bfloat16* Qhs = sm;

    const int tid = threadIdx.x, lane = tid & 31, warp = tid >> 5;
    const int grp = warp >> 2, wg = warp & 3, gtid = tid & 127;
    const size_t base = (size_t)blockIdx.y * Nn * DOUT;
    const int q0 = blockIdx.x * BQ;

    __nv_bfloat16* Kg = sm + QT + grp*4*KT;

    for (int idx = tid; idx < BQ*(D/8); idx += 512) {
        const int r = idx / (D/8), c = (idx % (D/8)) * 8;
        cp16(Qhs + r*DP + c, Qg + base + (size_t)(q0 + r) * DOUT + c);
    }
    asm volatile("cp.async.commit_group;\n" ::: "memory");

    auto stage = [&](int buf, int tt) {
        const int k0 = (NG*tt + grp) * BK;
        for (int idx = gtid; idx < BK*(D/8); idx += 128) {
            const int r = idx / (D/8), c = (idx % (D/8)) * 8;
            const size_t go = base + (size_t)(k0 + r) * DOUT + c;
            const int s = buf*KT + r*DP + c;
            cp16(Kg + s,        Kgm + go);
            cp16(Kg + 2*KT + s, Vgm + go);
        }
        asm volatile("cp.async.commit_group;\n" ::: "memory");
    };
    stage(0, 0);
    stage(1, 1);
    asm volatile("cp.async.wait_group 2;\n" ::: "memory");
    __syncthreads();

    const int mat = lane >> 3, rin = lane & 7;
    const unsigned sbase = (unsigned)__cvta_generic_to_shared(sm);
    const unsigned aQ = sbase
        + (unsigned)(((wg*16 + rin + ((mat & 1) << 3)) * DP + ((mat >> 1) << 3)) * 2);
    const unsigned kgb = sbase + (unsigned)((QT + grp*4*KT) * 2);
    const unsigned aK = kgb
        + (unsigned)(((rin + ((mat >> 1) << 3)) * DP + ((mat & 1) << 3)) * 2);
    const unsigned aV = kgb + (unsigned)(2*KT*2)
        + (unsigned)(((rin + ((mat & 1) << 3)) * DP + ((mat >> 1) << 3)) * 2);

    float o[16][4];
    #pragma unroll
    for (int i = 0; i < 16; i++) { o[i][0]=0.f; o[i][1]=0.f; o[i][2]=0.f; o[i][3]=0.f; }
    float ls0[4] = {0.f,0.f,0.f,0.f}, ls1[4] = {0.f,0.f,0.f,0.f};

    for (int tt = 0; tt < TTG; tt++) {
        if (tt == TTG-1) asm volatile("cp.async.wait_group 0;\n" ::: "memory");
        else             asm volatile("cp.async.wait_group 1;\n" ::: "memory");
        GBAR(1 + grp);
        const unsigned kb = (unsigned)((tt & 1) * KT * 2);

        #pragma unroll
        for (int hh = 0; hh < 4; hh++) {
            float sc[4][4];
            #pragma unroll
            for (int i = 0; i < 4; i++) { sc[i][0]=0.f; sc[i][1]=0.f; sc[i][2]=0.f; sc[i][3]=0.f; }
            #pragma unroll
            for (int k2 = 0; k2 < 2; k2++) {
                const int kt = 2*hh + k2;
                unsigned qa[4];
                ldsm4(qa, aQ + kt*32);
                unsigned bh[2][4];
                #pragma unroll
                for (int np = 0; np < 2; np++)
                    ldsm4(bh[np], aK + kb + (unsigned)((np*16*DP + kt*16) * 2));
                #pragma unroll
                for (int np = 0; np < 2; np++) {
                    mma_bf16(sc[2*np],   qa, bh[np][0], bh[np][1]);
                    mma_bf16(sc[2*np+1], qa, bh[np][2], bh[np][3]);
                }
            }
            #pragma unroll
            for (int nt = 0; nt < 4; nt++) {
                sc[nt][0] = ex2(sc[nt][0]);
                sc[nt][1] = ex2(sc[nt][1]);
                sc[nt][2] = ex2(sc[nt][2]);
                sc[nt][3] = ex2(sc[nt][3]);
                ls0[hh] += sc[nt][0] + sc[nt][1];
                ls1[hh] += sc[nt][2] + sc[nt][3];
            }
            #pragma unroll
            for (int kt2 = 0; kt2 < 2; kt2++) {
                unsigned pa[4];
                pa[0] = pack2(sc[2*kt2][0],   sc[2*kt2][1]);
                pa[1] = pack2(sc[2*kt2][2],   sc[2*kt2][3]);
                pa[2] = pack2(sc[2*kt2+1][0], sc[2*kt2+1][1]);
                pa[3] = pack2(sc[2*kt2+1][2], sc[2*kt2+1][3]);
                #pragma unroll
                for (int j = 0; j < 2; j++) {
                    const int np = 2*hh + j;
                    unsigned vh[4];
                    ldsm4t(vh, aV + kb + (unsigned)((kt2*16*DP + np*16) * 2));
                    mma_bf16(o[2*np],   pa, vh[0], vh[1]);
                    mma_bf16(o[2*np+1], pa, vh[2], vh[3]);
                }
            }
        }
        GBAR(1 + grp);
        if (tt + 2 < TTG) stage(tt & 1, tt + 2);
    }

    #pragma unroll
    for (int hh = 0; hh < 4; hh++) {
        ls0[hh] += __shfl_xor_sync(0xffffffffu, ls0[hh], 1);
        ls0[hh] += __shfl_xor_sync(0xffffffffu, ls0[hh], 2);
        ls1[hh] += __shfl_xor_sync(0xffffffffu, ls1[hh], 1);
        ls1[hh] += __shfl_xor_sync(0xffffffffu, ls1[hh], 2);
    }

    __syncthreads();
    float* mb = (float*)smraw;
    constexpr int MW = 8 + 64;
    if (grp > 0) {
        float* p = mb + ((grp-1)*128 + gtid)*MW;
        #pragma unroll
        for (int hh = 0; hh < 4; hh++) { p[hh] = ls0[hh]; p[4+hh] = ls1[hh]; }
        #pragma unroll
        for (int no = 0; no < 16; no++) {
            p[8+no*4+0] = o[no][0]; p[8+no*4+1] = o[no][1];
            p[8+no*4+2] = o[no][2]; p[8+no*4+3] = o[no][3];
        }
    }
    __syncthreads();
    if (grp == 0) {
        #pragma unroll
        for (int g2 = 0; g2 < NG-1; g2++) {
            const float* p = mb + (g2*128 + gtid)*MW;
            #pragma unroll
            for (int hh = 0; hh < 4; hh++) { ls0[hh] += p[hh]; ls1[hh] += p[4+hh]; }
            #pragma unroll
            for (int no = 0; no < 16; no++) {
                o[no][0] += p[8+no*4+0]; o[no][1] += p[8+no*4+1];
                o[no][2] += p[8+no*4+2]; o[no][3] += p[8+no*4+3];
            }
        }
        float i0[4], i1[4];
        #pragma unroll
        for (int hh = 0; hh < 4; hh++) { i0[hh] = 1.f/ls0[hh]; i1[hh] = 1.f/ls1[hh]; }
        const int rg = q0 + wg*16 + (lane >> 2);
        const int c0 = (lane & 3) * 2;
        #pragma unroll
        for (int no = 0; no < 16; no++) {
            const int hh = no >> 2;
            float v0 = fmaxf(o[no][0] * i0[hh], 0.f);
            float v1 = fmaxf(o[no][1] * i0[hh], 0.f);
            float v2 = fmaxf(o[no][2] * i1[hh], 0.f);
            float v3 = fmaxf(o[no][3] * i1[hh], 0.f);
            *(unsigned*)&Og[base + (size_t)rg*DOUT + no*8 + c0]     = pack2(v0, v1);
            *(unsigned*)&Og[base + (size_t)(rg+8)*DOUT + no*8 + c0] = pack2(v2, v3);
        }
    }
}

// ---------------- GAT2 attention + smem-staged residual add + LayerNorm -------
// LN fusion v2: grp 0 writes the NORMALIZED attention rows into a smem staging
// buffer (o registers die there), then ALL 16 warps run a lightweight LN phase
// (y = stage + proj; two warp reductions; write d_out). Avoids the round-8
// register blowup because no thread holds o while doing LN.
__global__ __launch_bounds__(512, 1) void attn2_mma(
    const __nv_bfloat16* __restrict__ Qg, const __nv_bfloat16* __restrict__ Kgm,
    const __nv_bfloat16* __restrict__ Vgm,
    const float* __restrict__ projg, const float* __restrict__ lng,
    const float* __restrict__ lnb, float* __restrict__ Og)
{
    constexpr int D = 128, BQ = 64, BK = 32, DP = D + 8;
    constexpr int NKT = D / 16, NPS = BK / 16, NT = BK / 8, NO = D / 8, NPV = D / 16;
    constexpr int QT = BQ * DP, KT = BK * DP;
    constexpr int NG = 4, TTG = Nn / BK / NG;

    extern __shared__ char smraw[];
    __nv_bfloat16* sm  = (__nv_bfloat16*)smraw;
    __nv_bfloat16* Qhs = sm;

    const int tid = threadIdx.x, lane = tid & 31, warp = tid >> 5;
    const int grp = warp >> 2, wg = warp & 3, gtid = tid & 127;
    const size_t base = (size_t)blockIdx.y * Nn * DOUT;
    const int q0 = blockIdx.x * BQ;

    __nv_bfloat16* Kg = sm + QT + grp*4*KT;

    for (int idx = tid; idx < BQ*(D/8); idx += 512) {
        const int r = idx / (D/8), c = (idx % (D/8)) * 8;
        cp16(Qhs + r*DP + c, Qg + base + (size_t)(q0 + r) * DOUT + c);
    }
    asm volatile("cp.async.commit_group;\n" ::: "memory");

    auto stage = [&](int buf, int tt) {
        const int k0 = (NG*tt + grp) * BK;
        for (int idx = gtid; idx < BK*(D/8); idx += 128) {
            const int r = idx / (D/8), c = (idx % (D/8)) * 8;
            const size_t go = base + (size_t)(k0 + r) * DOUT + c;
            const int s = buf*KT + r*DP + c;
            cp16(Kg + s,        Kgm + go);
            cp16(Kg + 2*KT + s, Vgm + go);
        }
        asm volatile("cp.async.commit_group;\n" ::: "memory");
    };
    stage(0, 0);
    stage(1, 1);
    asm volatile("cp.async.wait_group 2;\n" ::: "memory");
    __syncthreads();

    const int mat = lane >> 3, rin = lane & 7;
    const unsigned sbase = (unsigned)__cvta_generic_to_shared(sm);
    const unsigned aQ = sbase
        + (unsigned)(((wg*16 + rin + ((mat & 1) << 3)) * DP + ((mat >> 1) << 3)) * 2);
    const unsigned kgb = sbase + (unsigned)((QT + grp*4*KT) * 2);
    const unsigned aK = kgb
        + (unsigned)(((rin + ((mat >> 1) << 3)) * DP + ((mat & 1) << 3)) * 2);
    const unsigned aV = kgb + (unsigned)(2*KT*2)
        + (unsigned)(((rin + ((mat & 1) << 3)) * DP + ((mat >> 1) << 3)) * 2);

    float o[NO][4];
    #pragma unroll
    for (int i = 0; i < NO; i++) { o[i][0]=0.f; o[i][1]=0.f; o[i][2]=0.f; o[i][3]=0.f; }
    float ls0 = 0.f, ls1 = 0.f;

    for (int tt = 0; tt < TTG; tt++) {
        if (tt == TTG-1) asm volatile("cp.async.wait_group 0;\n" ::: "memory");
        else             asm volatile("cp.async.wait_group 1;\n" ::: "memory");
        GBAR(1 + grp);
        const unsigned kb = (unsigned)((tt & 1) * KT * 2);

        float sc[NT][4];
        #pragma unroll
        for (int i = 0; i < NT; i++) { sc[i][0]=0.f; sc[i][1]=0.f; sc[i][2]=0.f; sc[i][3]=0.f; }

        #pragma unroll
        for (int kt = 0; kt < NKT; kt++) {
            unsigned qa[4];
            ldsm4(qa, aQ + kt*32);
            unsigned bh[NPS][4];
            #pragma unroll
            for (int np = 0; np < NPS; np++)
                ldsm4(bh[np], aK + kb + (unsigned)((np*16*DP + kt*16) * 2));
            #pragma unroll
            for (int np = 0; np < NPS; np++) {
                mma_bf16(sc[2*np],   qa, bh[np][0], bh[np][1]);
                mma_bf16(sc[2*np+1], qa, bh[np][2], bh[np][3]);
            }
        }

        #pragma unroll
        for (int nt = 0; nt < NT; nt++) {
            sc[nt][0] = ex2(sc[nt][0]);
            sc[nt][1] = ex2(sc[nt][1]);
            sc[nt][2] = ex2(sc[nt][2]);
            sc[nt][3] = ex2(sc[nt][3]);
            ls0 += sc[nt][0] + sc[nt][1];
            ls1 += sc[nt][2] + sc[nt][3];
        }

        #pragma unroll
        for (int kt2 = 0; kt2 < NPS; kt2++) {
            unsigned pa[4];
            pa[0] = pack2(sc[2*kt2][0],   sc[2*kt2][1]);
            pa[1] = pack2(sc[2*kt2][2],   sc[2*kt2][3]);
            pa[2] = pack2(sc[2*kt2+1][0], sc[2*kt2+1][1]);
            pa[3] = pack2(sc[2*kt2+1][2], sc[2*kt2+1][3]);
            #pragma unroll
            for (int np = 0; np < NPV; np++) {
                unsigned vh[4];
                ldsm4t(vh, aV + kb + (unsigned)((kt2*16*DP + np*16) * 2));
                mma_bf16(o[2*np],   pa, vh[0], vh[1]);
                mma_bf16(o[2*np+1], pa, vh[2], vh[3]);
            }
        }
        GBAR(1 + grp);
        if (tt + 2 < TTG) stage(tt & 1, tt + 2);
    }

    ls0 += __shfl_xor_sync(0xffffffffu, ls0, 1);
    ls0 += __shfl_xor_sync(0xffffffffu, ls0, 2);
    ls1 += __shfl_xor_sync(0xffffffffu, ls1, 1);
    ls1 += __shfl_xor_sync(0xffffffffu, ls1, 2);

    // ---- merge the four group partials in smem, grp 0 normalizes to ybuf ----
    __syncthreads();
    float* mb = (float*)smraw;
    constexpr int MW = 2 + NO*4;                 // 66
    float* ybuf = mb + 3*128*MW;                 // 64 x 128 fp32 staging (32 KB)
    if (grp > 0) {
        float* p = mb + ((grp-1)*128 + gtid)*MW;
        p[0] = ls0; p[1] = ls1;
        #pragma unroll
        for (int no = 0; no < NO; no++) {
            p[2+no*4+0] = o[no][0]; p[2+no*4+1] = o[no][1];
            p[2+no*4+2] = o[no][2]; p[2+no*4+3] = o[no][3];
        }
    }
    __syncthreads();
    if (grp == 0) {
        #pragma unroll
        for (int g2 = 0; g2 < NG-1; g2++) {
            const float* p = mb + (g2*128 + gtid)*MW;
            ls0 += p[0]; ls1 += p[1];
            #pragma unroll
            for (int no = 0; no < NO; no++) {
                o[no][0] += p[2+no*4+0]; o[no][1] += p[2+no*4+1];
                o[no][2] += p[2+no*4+2]; o[no][3] += p[2+no*4+3];
            }
        }
        const float i0 = 1.f / ls0, i1 = 1.f / ls1;
        const int rl = wg*16 + (lane >> 2);      // local row 0..63
        const int c0 = (lane & 3) * 2;
        #pragma unroll
        for (int no = 0; no < NO; no++) {
            *(float2*)&ybuf[rl*DOUT + no*8 + c0] =
                make_float2(o[no][0]*i0, o[no][1]*i0);
            *(float2*)&ybuf[(rl+8)*DOUT + no*8 + c0] =
                make_float2(o[no][2]*i1, o[no][3]*i1);
        }
    }
    __syncthreads();

    // ---- LN phase: all 16 warps, 4 rows each, lane owns 4 cols (float4) ----
    #pragma unroll
    for (int r = 0; r < 4; r++) {
        const int rr = warp*4 + r;               // local row 0..63
        float4 y4 = *(float4*)&ybuf[rr*DOUT + lane*4];
        const float4 p4 = *(const float4*)&projg[base + (size_t)(q0+rr)*DOUT + lane*4];
        y4.x += p4.x; y4.y += p4.y; y4.z += p4.z; y4.w += p4.w;
        float s  = y4.x + y4.y + y4.z + y4.w;
        float s2 = y4.x*y4.x + y4.y*y4.y + y4.z*y4.z + y4.w*y4.w;
        #pragma unroll
        for (int off = 16; off > 0; off >>= 1) {
            s  += __shfl_xor_sync(0xffffffffu, s,  off);
            s2 += __shfl_xor_sync(0xffffffffu, s2, off);
        }
        const float mu = s * (1.f/128.f);
        const float rv = rsqrtf(s2*(1.f/128.f) - mu*mu + 1e-3f);
        const float4 g4 = *(const float4*)&lng[lane*4];
        const float4 b4 = *(const float4*)&lnb[lane*4];
        float4 out4;
        out4.x = (y4.x - mu)*rv*g4.x + b4.x;
        out4.y = (y4.y - mu)*rv*g4.y + b4.y;
        out4.z = (y4.z - mu)*rv*g4.z + b4.z;
        out4.w = (y4.w - mu)*rv*g4.w + b4.w;
        *(float4*)&Og[base + (size_t)(q0+rr)*DOUT + lane*4] = out4;
    }
}

// ---------------- launch -------------------------------------------------------
extern "C" void kernel_launch(void* const* d_in, const int* in_sizes, int n_in,
                              void* d_out, int out_size)
{
    (void)in_sizes; (void)n_in; (void)out_size;
    const float* x   = (const float*)d_in[0];
    // d_in[1] = emb : unused (adjacency mask is a provable no-op)
    const float* q1w = (const float*)d_in[2];
    const float* q1b = (const float*)d_in[3];
    const float* k1w = (const float*)d_in[4];
    const float* k1b = (const float*)d_in[5];
    const float* v1w = (const float*)d_in[6];
    const float* v1b = (const float*)d_in[7];
    const float* q2w = (const float*)d_in[8];
    const float* q2b = (const float*)d_in[9];
    const float* k2w = (const float*)d_in[10];
    const float* k2b = (const float*)d_in[11];
    const float* v2w = (const float*)d_in[12];
    const float* v2b = (const float*)d_in[13];
    const float* pw  = (const float*)d_in[14];
    const float* lng = (const float*)d_in[15];
    const float* lnb = (const float*)d_in[16];
    float* out = (float*)d_out;

    Scratch* sp = nullptr;
    cudaGetSymbolAddress((void**)&sp, g_s);

    const int SMEM_A  = (64*136 + 16*32*136) * 2;            // 156672 B (attn)
    const int SMEM_Q1 = (2*128*72 + 2*64*136) * 2;           //  71680 B
    const int SMEM_Q2 = (2*128*136) * 2;                     //  69632 B
    cudaFuncSetAttribute(attn1_4h,
                         cudaFuncAttributeMaxDynamicSharedMemorySize, SMEM_A);
    cudaFuncSetAttribute(attn2_mma,
                         cudaFuncAttributeMaxDynamicSharedMemorySize, SMEM_A);
    cudaFuncSetAttribute(qkv1_mma,
                         cudaFuncAttributeMaxDynamicSharedMemorySize, SMEM_Q1);
    cudaFuncSetAttribute(qkv2_mma,
                         cudaFuncAttributeMaxDynamicSharedMemorySize, SMEM_Q2);

    qkv1_mma<<<dim3(ROWS/128, 4), 256, SMEM_Q1>>>(x, q1w,q1b, k1w,k1b, v1w,v1b,
        pw, sp->q1, sp->k1, sp->v1, sp->proj);

    attn1_4h<<<dim3(Nn/64, Bn), 512, SMEM_A>>>(sp->q1, sp->k1, sp->v1, sp->h);

    qkv2_mma<<<dim3(ROWS/128, 3), 256, SMEM_Q2>>>(sp->h, q2w,q2b, k2w,k2b,
        v2w,v2b, sp->q2, sp->k2, sp->v2);

    attn2_mma<<<dim3(Nn/64, Bn), 512, SMEM_A>>>(sp->q2, sp->k2, sp->v2,
        sp->proj, lng, lnb, out);
}

// round 13
// speedup vs baseline: 1.6130x; 1.0565x over previous
#include <cuda_runtime.h>
#include <cuda_bf16.h>
#include <math.h>

#define Bn   4
#define Nn   2048
#define FIN  64
#define DOUT 128
#define ROWS (Bn*Nn)   // 8192

// ---------------- scratch (device globals; no allocation allowed) ----------
struct Scratch {
    __nv_bfloat16 q1[ROWS*DOUT], k1[ROWS*DOUT], v1[ROWS*DOUT];
    __nv_bfloat16 q2[ROWS*DOUT], k2[ROWS*DOUT], v2[ROWS*DOUT];
    float proj[ROWS*DOUT];
};
__device__ Scratch g_s;

// ---------------- helpers ----------------------------------------------------
__device__ __forceinline__ void cp16(const __nv_bfloat16* s, const __nv_bfloat16* g) {
    unsigned sa = (unsigned)__cvta_generic_to_shared((void*)s);
    asm volatile("cp.async.cg.shared.global [%0], [%1], 16;\n" :: "r"(sa), "l"(g));
}

__device__ __forceinline__ void ldsm4(unsigned* r, unsigned a) {
    asm volatile("ldmatrix.sync.aligned.m8n8.x4.shared.b16 {%0,%1,%2,%3}, [%4];\n"
        : "=r"(r[0]), "=r"(r[1]), "=r"(r[2]), "=r"(r[3]) : "r"(a));
}
__device__ __forceinline__ void ldsm4t(unsigned* r, unsigned a) {
    asm volatile("ldmatrix.sync.aligned.m8n8.x4.trans.shared.b16 {%0,%1,%2,%3}, [%4];\n"
        : "=r"(r[0]), "=r"(r[1]), "=r"(r[2]), "=r"(r[3]) : "r"(a));
}

__device__ __forceinline__ void mma_bf16(float* c, const unsigned* a,
                                         unsigned b0, unsigned b1) {
    asm volatile("mma.sync.aligned.m16n8k16.row.col.f32.bf16.bf16.f32 "
        "{%0,%1,%2,%3}, {%4,%5,%6,%7}, {%8,%9}, {%0,%1,%2,%3};\n"
        : "+f"(c[0]), "+f"(c[1]), "+f"(c[2]), "+f"(c[3])
        : "r"(a[0]), "r"(a[1]), "r"(a[2]), "r"(a[3]), "r"(b0), "r"(b1));
}

__device__ __forceinline__ unsigned pack2(float x0, float x1) {
    unsigned h;
    asm("cvt.rn.bf16x2.f32 %0, %1, %2;\n" : "=r"(h) : "f"(x1), "f"(x0));
    return h;
}

__device__ __forceinline__ float ex2(float x) {
    float y; asm("ex2.approx.ftz.f32 %0, %1;\n" : "=f"(y) : "f"(x)); return y;
}

#define GBAR(id) asm volatile("bar.sync %0, %1;" :: "r"(id), "r"(128) : "memory")

// ---------------- QKV1 + proj tensor-core GEMM --------------------------------
// C[8192,128] = x[8192,64] @ w[64,128]; blockIdx.y selects {q,k,v,proj}.
// q/k/v: single bf16. proj: 3xBF16 split -> fp32 (residual path stays exact).
__global__ __launch_bounds__(256) void qkv1_mma(
    const float* __restrict__ x,
    const float* __restrict__ qw, const float* __restrict__ qb,
    const float* __restrict__ kw, const float* __restrict__ kb,
    const float* __restrict__ vw, const float* __restrict__ vb,
    const float* __restrict__ pw,
    __nv_bfloat16* __restrict__ qo, __nv_bfloat16* __restrict__ ko,
    __nv_bfloat16* __restrict__ vo, float* __restrict__ po)
{
    const int y = blockIdx.y;
    const float* w    = (y==0) ? qw : (y==1) ? kw : (y==2) ? vw : pw;
    const float* bias = (y==0) ? qb : (y==1) ? kb : vb;   // unused for proj
    const bool proj = (y == 3);

    extern __shared__ __nv_bfloat16 smq[];
    __nv_bfloat16* Xh = smq;               // 128 x 72
    __nv_bfloat16* Xl = Xh + 128*72;       // 128 x 72 (proj only)
    __nv_bfloat16* Wh = Xl + 128*72;       // 64 x 136
    __nv_bfloat16* Wl = Wh + 64*136;       // 64 x 136 (proj only)

    const int tid = threadIdx.x, lane = tid & 31, warp = tid >> 5;
    const int r0 = blockIdx.x * 128;
    const int mat = lane >> 3, rin = lane & 7;

    for (int idx = tid; idx < 128*FIN; idx += 256) {
        const int r = idx >> 6, c = idx & 63;
        const float v = x[(size_t)(r0+r)*FIN + c];
        const __nv_bfloat16 hv = __float2bfloat16(v);
        Xh[r*72 + c] = hv;
        Xl[r*72 + c] = __float2bfloat16(v - __bfloat162float(hv));
    }
    for (int idx = tid; idx < FIN*128; idx += 256) {
        const int r = idx >> 7, c = idx & 127;
        const float v = w[(size_t)r*DOUT + c];
        const __nv_bfloat16 hv = __float2bfloat16(v);
        Wh[r*136 + c] = hv;
        Wl[r*136 + c] = __float2bfloat16(v - __bfloat162float(hv));
    }
    __syncthreads();

    const unsigned aX = (unsigned)__cvta_generic_to_shared(Xh)
        + (unsigned)(((warp*16 + rin + ((mat & 1) << 3)) * 72 + ((mat >> 1) << 3)) * 2);
    const unsigned aW = (unsigned)__cvta_generic_to_shared(Wh)
        + (unsigned)(((rin + ((mat & 1) << 3)) * 136 + ((mat >> 1) << 3)) * 2);
    const unsigned oXl = (unsigned)(128*72*2);
    const unsigned oWl = (unsigned)(64*136*2);

    float o[16][4];
    #pragma unroll
    for (int i = 0; i < 16; i++) { o[i][0]=0.f; o[i][1]=0.f; o[i][2]=0.f; o[i][3]=0.f; }

    #pragma unroll
    for (int kt = 0; kt < 4; kt++) {
        unsigned ah[4], al[4];
        ldsm4(ah, aX + kt*32);
        if (proj) ldsm4(al, aX + oXl + kt*32);
        #pragma unroll
        for (int np = 0; np < 8; np++) {
            const unsigned off = (unsigned)((kt*16*136 + np*16) * 2);
            unsigned bh[4];
            ldsm4t(bh, aW + off);
            mma_bf16(o[2*np],   ah, bh[0], bh[1]);
            mma_bf16(o[2*np+1], ah, bh[2], bh[3]);
            if (proj) {
                unsigned bl[4];
                ldsm4t(bl, aW + oWl + off);
                mma_bf16(o[2*np],   ah, bl[0], bl[1]);
                mma_bf16(o[2*np+1], ah, bl[2], bl[3]);
                mma_bf16(o[2*np],   al, bh[0], bh[1]);
                mma_bf16(o[2*np+1], al, bh[2], bh[3]);
            }
        }
    }

    const int rg = r0 + warp*16 + (lane >> 2);
    const int c0 = (lane & 3) * 2;
    if (proj) {
        #pragma unroll
        for (int no = 0; no < 16; no++) {
            *(float2*)&po[(size_t)rg*DOUT + no*8 + c0]     = make_float2(o[no][0], o[no][1]);
            *(float2*)&po[(size_t)(rg+8)*DOUT + no*8 + c0] = make_float2(o[no][2], o[no][3]);
        }
    } else {
        const float scale = (y==0) ? 0.17677669529663689f * 1.4426950408889634f : 1.f;
        __nv_bfloat16* outp = (y==0) ? qo : (y==1) ? ko : vo;
        #pragma unroll
        for (int no = 0; no < 16; no++) {
            const float b0 = bias[no*8 + c0], b1 = bias[no*8 + c0 + 1];
            *(unsigned*)&outp[(size_t)rg*DOUT + no*8 + c0] =
                pack2((o[no][0]+b0)*scale, (o[no][1]+b1)*scale);
            *(unsigned*)&outp[(size_t)(rg+8)*DOUT + no*8 + c0] =
                pack2((o[no][2]+b0)*scale, (o[no][3]+b1)*scale);
        }
    }
}

// ---------------- GAT1 (4 heads, block-diagonal) + fused QKV2 epilogue --------
// Mainloop identical to round 10. Epilogue (smem-staged, round-12 recipe):
// grp0 writes ReLU'd h rows (bf16) to smem stage -> all threads convert the
// three 128x128 qkv2 weight panels to bf16 smem -> 12 warps run the
// M=64,N=384,K=128 GEMM -> write q2/k2/v2 directly. No h gmem round-trip,
// no separate qkv2 kernel.
__global__ __launch_bounds__(512, 1) void attn1_4h(
    const __nv_bfloat16* __restrict__ Qg, const __nv_bfloat16* __restrict__ Kgm,
    const __nv_bfloat16* __restrict__ Vgm,
    const float* __restrict__ q2w, const float* __restrict__ q2b,
    const float* __restrict__ k2w, const float* __restrict__ k2b,
    const float* __restrict__ v2w, const float* __restrict__ v2b,
    __nv_bfloat16* __restrict__ q2o, __nv_bfloat16* __restrict__ k2o,
    __nv_bfloat16* __restrict__ v2o)
{
    constexpr int D = 128, BQ = 64, BK = 32, DP = D + 8;
    constexpr int QT = BQ * DP, KT = BK * DP;
    constexpr int NG = 4, TTG = Nn / BK / NG;   // 16
    constexpr int MW = 8 + 64;                  // merge record floats
    constexpr int HS_OFF = 3*128*MW*4;          // byte offset of h stage (110592)

    extern __shared__ char smraw[];
    __nv_bfloat16* sm  = (__nv_bfloat16*)smraw;
    __nv_bfloat16* Qhs = sm;

    const int tid = threadIdx.x, lane = tid & 31, warp = tid >> 5;
    const int grp = warp >> 2, wg = warp & 3, gtid = tid & 127;
    const size_t base = (size_t)blockIdx.y * Nn * DOUT;
    const int q0 = blockIdx.x * BQ;

    __nv_bfloat16* Kg = sm + QT + grp*4*KT;

    for (int idx = tid; idx < BQ*(D/8); idx += 512) {
        const int r = idx / (D/8), c = (idx % (D/8)) * 8;
        cp16(Qhs + r*DP + c, Qg + base + (size_t)(q0 + r) * DOUT + c);
    }
    asm volatile("cp.async.commit_group;\n" ::: "memory");

    auto stage = [&](int buf, int tt) {
        const int k0 = (NG*tt + grp) * BK;
        for (int idx = gtid; idx < BK*(D/8); idx += 128) {
            const int r = idx / (D/8), c = (idx % (D/8)) * 8;
            const size_t go = base + (size_t)(k0 + r) * DOUT + c;
            const int s = buf*KT + r*DP + c;
            cp16(Kg + s,        Kgm + go);
            cp16(Kg + 2*KT + s, Vgm + go);
        }
        asm volatile("cp.async.commit_group;\n" ::: "memory");
    };
    stage(0, 0);
    stage(1, 1);
    asm volatile("cp.async.wait_group 2;\n" ::: "memory");
    __syncthreads();

    const int mat = lane >> 3, rin = lane & 7;
    const unsigned sbase = (unsigned)__cvta_generic_to_shared(sm);
    const unsigned aQ = sbase
        + (unsigned)(((wg*16 + rin + ((mat & 1) << 3)) * DP + ((mat >> 1) << 3)) * 2);
    const unsigned kgb = sbase + (unsigned)((QT + grp*4*KT) * 2);
    const unsigned aK = kgb
        + (unsigned)(((rin + ((mat >> 1) << 3)) * DP + ((mat & 1) << 3)) * 2);
    const unsigned aV = kgb + (unsigned)(2*KT*2)
        + (unsigned)(((rin + ((mat & 1) << 3)) * DP + ((mat >> 1) << 3)) * 2);

    float o[16][4];
    #pragma unroll
    for (int i = 0; i < 16; i++) { o[i][0]=0.f; o[i][1]=0.f; o[i][2]=0.f; o[i][3]=0.f; }
    float ls0[4] = {0.f,0.f,0.f,0.f}, ls1[4] = {0.f,0.f,0.f,0.f};

    for (int tt = 0; tt < TTG; tt++) {
        if (tt == TTG-1) asm volatile("cp.async.wait_group 0;\n" ::: "memory");
        else             asm volatile("cp.async.wait_group 1;\n" ::: "memory");
        GBAR(1 + grp);
        const unsigned kb = (unsigned)((tt & 1) * KT * 2);

        #pragma unroll
        for (int hh = 0; hh < 4; hh++) {
            float sc[4][4];
            #pragma unroll
            for (int i = 0; i < 4; i++) { sc[i][0]=0.f; sc[i][1]=0.f; sc[i][2]=0.f; sc[i][3]=0.f; }
            #pragma unroll
            for (int k2 = 0; k2 < 2; k2++) {
                const int kt = 2*hh + k2;
                unsigned qa[4];
                ldsm4(qa, aQ + kt*32);
                unsigned bh[2][4];
                #pragma unroll
                for (int np = 0; np < 2; np++)
                    ldsm4(bh[np], aK + kb + (unsigned)((np*16*DP + kt*16) * 2));
                #pragma unroll
                for (int np = 0; np < 2; np++) {
                    mma_bf16(sc[2*np],   qa, bh[np][0], bh[np][1]);
                    mma_bf16(sc[2*np+1], qa, bh[np][2], bh[np][3]);
                }
            }
            #pragma unroll
            for (int nt = 0; nt < 4; nt++) {
                sc[nt][0] = ex2(sc[nt][0]);
                sc[nt][1] = ex2(sc[nt][1]);
                sc[nt][2] = ex2(sc[nt][2]);
                sc[nt][3] = ex2(sc[nt][3]);
                ls0[hh] += sc[nt][0] + sc[nt][1];
                ls1[hh] += sc[nt][2] + sc[nt][3];
            }
            #pragma unroll
            for (int kt2 = 0; kt2 < 2; kt2++) {
                unsigned pa[4];
                pa[0] = pack2(sc[2*kt2][0],   sc[2*kt2][1]);
                pa[1] = pack2(sc[2*kt2][2],   sc[2*kt2][3]);
                pa[2] = pack2(sc[2*kt2+1][0], sc[2*kt2+1][1]);
                pa[3] = pack2(sc[2*kt2+1][2], sc[2*kt2+1][3]);
                #pragma unroll
                for (int j = 0; j < 2; j++) {
                    const int np = 2*hh + j;
                    unsigned vh[4];
                    ldsm4t(vh, aV + kb + (unsigned)((kt2*16*DP + np*16) * 2));
                    mma_bf16(o[2*np],   pa, vh[0], vh[1]);
                    mma_bf16(o[2*np+1], pa, vh[2], vh[3]);
                }
            }
        }
        GBAR(1 + grp);
        if (tt + 2 < TTG) stage(tt & 1, tt + 2);
    }

    #pragma unroll
    for (int hh = 0; hh < 4; hh++) {
        ls0[hh] += __shfl_xor_sync(0xffffffffu, ls0[hh], 1);
        ls0[hh] += __shfl_xor_sync(0xffffffffu, ls0[hh], 2);
        ls1[hh] += __shfl_xor_sync(0xffffffffu, ls1[hh], 1);
        ls1[hh] += __shfl_xor_sync(0xffffffffu, ls1[hh], 2);
    }

    // ---- merge partials; grp0 writes ReLU'd h rows into smem stage ----
    __syncthreads();
    float* mb = (float*)smraw;
    __nv_bfloat16* hs = (__nv_bfloat16*)(smraw + HS_OFF);   // 64 x 136 bf16
    if (grp > 0) {
        float* p = mb + ((grp-1)*128 + gtid)*MW;
        #pragma unroll
        for (int hh = 0; hh < 4; hh++) { p[hh] = ls0[hh]; p[4+hh] = ls1[hh]; }
        #pragma unroll
        for (int no = 0; no < 16; no++) {
            p[8+no*4+0] = o[no][0]; p[8+no*4+1] = o[no][1];
            p[8+no*4+2] = o[no][2]; p[8+no*4+3] = o[no][3];
        }
    }
    __syncthreads();
    if (grp == 0) {
        #pragma unroll
        for (int g2 = 0; g2 < NG-1; g2++) {
            const float* p = mb + (g2*128 + gtid)*MW;
            #pragma unroll
            for (int hh = 0; hh < 4; hh++) { ls0[hh] += p[hh]; ls1[hh] += p[4+hh]; }
            #pragma unroll
            for (int no = 0; no < 16; no++) {
                o[no][0] += p[8+no*4+0]; o[no][1] += p[8+no*4+1];
                o[no][2] += p[8+no*4+2]; o[no][3] += p[8+no*4+3];
            }
        }
        float i0[4], i1[4];
        #pragma unroll
        for (int hh = 0; hh < 4; hh++) { i0[hh] = 1.f/ls0[hh]; i1[hh] = 1.f/ls1[hh]; }
        const int rl = wg*16 + (lane >> 2);      // local row 0..63
        const int c0 = (lane & 3) * 2;
        #pragma unroll
        for (int no = 0; no < 16; no++) {
            const int hh = no >> 2;
            float v0 = fmaxf(o[no][0] * i0[hh], 0.f);
            float v1 = fmaxf(o[no][1] * i0[hh], 0.f);
            float v2 = fmaxf(o[no][2] * i1[hh], 0.f);
            float v3 = fmaxf(o[no][3] * i1[hh], 0.f);
            *(unsigned*)&hs[rl*136 + no*8 + c0]     = pack2(v0, v1);
            *(unsigned*)&hs[(rl+8)*136 + no*8 + c0] = pack2(v2, v3);
        }
    }
    __syncthreads();

    // ---- convert qkv2 weights to bf16 smem (merge region is dead now) ----
    __nv_bfloat16* ws = (__nv_bfloat16*)smraw;   // 3 panels of 128x136
    for (int idx = tid; idx < 3*128*32; idx += 512) {
        const int p = idx >> 12, r = (idx >> 5) & 127, c4 = idx & 31;
        const float* wp = (p==0) ? q2w : (p==1) ? k2w : v2w;
        const float4 w4 = *(const float4*)&wp[(size_t)r*DOUT + c4*4];
        *(unsigned*)&ws[p*128*136 + r*136 + c4*4]     = pack2(w4.x, w4.y);
        *(unsigned*)&ws[p*128*136 + r*136 + c4*4 + 2] = pack2(w4.z, w4.w);
    }
    __syncthreads();

    // ---- qkv2 GEMM: 12 warps, warp = (mw 0..3) x (panel p 0..2) ----
    const int mw = warp & 3, pp = warp >> 2;
    if (pp < 3) {
        const unsigned aH = sbase + (unsigned)HS_OFF
            + (unsigned)(((mw*16 + rin + ((mat & 1) << 3)) * 136 + ((mat >> 1) << 3)) * 2);
        const unsigned aW2 = sbase
            + (unsigned)((pp*128*136 + (rin + ((mat & 1) << 3)) * 136 + ((mat >> 1) << 3)) * 2);

        float acc[16][4];
        #pragma unroll
        for (int i = 0; i < 16; i++) { acc[i][0]=0.f; acc[i][1]=0.f; acc[i][2]=0.f; acc[i][3]=0.f; }

        #pragma unroll
        for (int kt = 0; kt < 8; kt++) {
            unsigned a4[4];
            ldsm4(a4, aH + kt*32);
            #pragma unroll
            for (int np = 0; np < 8; np++) {
                unsigned b4[4];
                ldsm4t(b4, aW2 + (unsigned)((kt*16*136 + np*16) * 2));
                mma_bf16(acc[2*np],   a4, b4[0], b4[1]);
                mma_bf16(acc[2*np+1], a4, b4[2], b4[3]);
            }
        }

        const float* bias = (pp==0) ? q2b : (pp==1) ? k2b : v2b;
        __nv_bfloat16* outp = (pp==0) ? q2o : (pp==1) ? k2o : v2o;
        const float scale = (pp==0) ?
            0.08838834764831845f * 1.4426950408889634f : 1.f;   // log2e/sqrt(128)
        const int rg = q0 + mw*16 + (lane >> 2);
        const int c0 = (lane & 3) * 2;
        #pragma unroll
        for (int no = 0; no < 16; no++) {
            const float b0 = bias[no*8 + c0], b1 = bias[no*8 + c0 + 1];
            *(unsigned*)&outp[base + (size_t)rg*DOUT + no*8 + c0] =
                pack2((acc[no][0]+b0)*scale, (acc[no][1]+b1)*scale);
            *(unsigned*)&outp[base + (size_t)(rg+8)*DOUT + no*8 + c0] =
                pack2((acc[no][2]+b0)*scale, (acc[no][3]+b1)*scale);
        }
    }
}

// ---------------- GAT2 attention + smem-staged residual add + LayerNorm -------
__global__ __launch_bounds__(512, 1) void attn2_mma(
    const __nv_bfloat16* __restrict__ Qg, const __nv_bfloat16* __restrict__ Kgm,
    const __nv_bfloat16* __restrict__ Vgm,
    const float* __restrict__ projg, const float* __restrict__ lng,
    const float* __restrict__ lnb, float* __restrict__ Og)
{
    constexpr int D = 128, BQ = 64, BK = 32, DP = D + 8;
    constexpr int NKT = D / 16, NPS = BK / 16, NT = BK / 8, NO = D / 8, NPV = D / 16;
    constexpr int QT = BQ * DP, KT = BK * DP;
    constexpr int NG = 4, TTG = Nn / BK / NG;

    extern __shared__ char smraw[];
    __nv_bfloat16* sm  = (__nv_bfloat16*)smraw;
    __nv_bfloat16* Qhs = sm;

    const int tid = threadIdx.x, lane = tid & 31, warp = tid >> 5;
    const int grp = warp >> 2, wg = warp & 3, gtid = tid & 127;
    const size_t base = (size_t)blockIdx.y * Nn * DOUT;
    const int q0 = blockIdx.x * BQ;

    __nv_bfloat16* Kg = sm + QT + grp*4*KT;

    for (int idx = tid; idx < BQ*(D/8); idx += 512) {
        const int r = idx / (D/8), c = (idx % (D/8)) * 8;
        cp16(Qhs + r*DP + c, Qg + base + (size_t)(q0 + r) * DOUT + c);
    }
    asm volatile("cp.async.commit_group;\n" ::: "memory");

    auto stage = [&](int buf, int tt) {
        const int k0 = (NG*tt + grp) * BK;
        for (int idx = gtid; idx < BK*(D/8); idx += 128) {
            const int r = idx / (D/8), c = (idx % (D/8)) * 8;
            const size_t go = base + (size_t)(k0 + r) * DOUT + c;
            const int s = buf*KT + r*DP + c;
            cp16(Kg + s,        Kgm + go);
            cp16(Kg + 2*KT + s, Vgm + go);
        }
        asm volatile("cp.async.commit_group;\n" ::: "memory");
    };
    stage(0, 0);
    stage(1, 1);
    asm volatile("cp.async.wait_group 2;\n" ::: "memory");
    __syncthreads();

    const int mat = lane >> 3, rin = lane & 7;
    const unsigned sbase = (unsigned)__cvta_generic_to_shared(sm);
    const unsigned aQ = sbase
        + (unsigned)(((wg*16 + rin + ((mat & 1) << 3)) * DP + ((mat >> 1) << 3)) * 2);
    const unsigned kgb = sbase + (unsigned)((QT + grp*4*KT) * 2);
    const unsigned aK = kgb
        + (unsigned)(((rin + ((mat >> 1) << 3)) * DP + ((mat & 1) << 3)) * 2);
    const unsigned aV = kgb + (unsigned)(2*KT*2)
        + (unsigned)(((rin + ((mat & 1) << 3)) * DP + ((mat >> 1) << 3)) * 2);

    float o[NO][4];
    #pragma unroll
    for (int i = 0; i < NO; i++) { o[i][0]=0.f; o[i][1]=0.f; o[i][2]=0.f; o[i][3]=0.f; }
    float ls0 = 0.f, ls1 = 0.f;

    for (int tt = 0; tt < TTG; tt++) {
        if (tt == TTG-1) asm volatile("cp.async.wait_group 0;\n" ::: "memory");
        else             asm volatile("cp.async.wait_group 1;\n" ::: "memory");
        GBAR(1 + grp);
        const unsigned kb = (unsigned)((tt & 1) * KT * 2);

        float sc[NT][4];
        #pragma unroll
        for (int i = 0; i < NT; i++) { sc[i][0]=0.f; sc[i][1]=0.f; sc[i][2]=0.f; sc[i][3]=0.f; }

        #pragma unroll
        for (int kt = 0; kt < NKT; kt++) {
            unsigned qa[4];
            ldsm4(qa, aQ + kt*32);
            unsigned bh[NPS][4];
            #pragma unroll
            for (int np = 0; np < NPS; np++)
                ldsm4(bh[np], aK + kb + (unsigned)((np*16*DP + kt*16) * 2));
            #pragma unroll
            for (int np = 0; np < NPS; np++) {
                mma_bf16(sc[2*np],   qa, bh[np][0], bh[np][1]);
                mma_bf16(sc[2*np+1], qa, bh[np][2], bh[np][3]);
            }
        }

        #pragma unroll
        for (int nt = 0; nt < NT; nt++) {
            sc[nt][0] = ex2(sc[nt][0]);
            sc[nt][1] = ex2(sc[nt][1]);
            sc[nt][2] = ex2(sc[nt][2]);
            sc[nt][3] = ex2(sc[nt][3]);
            ls0 += sc[nt][0] + sc[nt][1];
            ls1 += sc[nt][2] + sc[nt][3];
        }

        #pragma unroll
        for (int kt2 = 0; kt2 < NPS; kt2++) {
            unsigned pa[4];
            pa[0] = pack2(sc[2*kt2][0],   sc[2*kt2][1]);
            pa[1] = pack2(sc[2*kt2][2],   sc[2*kt2][3]);
            pa[2] = pack2(sc[2*kt2+1][0], sc[2*kt2+1][1]);
            pa[3] = pack2(sc[2*kt2+1][2], sc[2*kt2+1][3]);
            #pragma unroll
            for (int np = 0; np < NPV; np++) {
                unsigned vh[4];
                ldsm4t(vh, aV + kb + (unsigned)((kt2*16*DP + np*16) * 2));
                mma_bf16(o[2*np],   pa, vh[0], vh[1]);
                mma_bf16(o[2*np+1], pa, vh[2], vh[3]);
            }
        }
        GBAR(1 + grp);
        if (tt + 2 < TTG) stage(tt & 1, tt + 2);
    }

    ls0 += __shfl_xor_sync(0xffffffffu, ls0, 1);
    ls0 += __shfl_xor_sync(0xffffffffu, ls0, 2);
    ls1 += __shfl_xor_sync(0xffffffffu, ls1, 1);
    ls1 += __shfl_xor_sync(0xffffffffu, ls1, 2);

    // ---- merge the four group partials in smem, grp 0 normalizes to ybuf ----
    __syncthreads();
    float* mb = (float*)smraw;
    constexpr int MW = 2 + NO*4;                 // 66
    float* ybuf = mb + 3*128*MW;                 // 64 x 128 fp32 staging (32 KB)
    if (grp > 0) {
        float* p = mb + ((grp-1)*128 + gtid)*MW;
        p[0] = ls0; p[1] = ls1;
        #pragma unroll
        for (int no = 0; no < NO; no++) {
            p[2+no*4+0] = o[no][0]; p[2+no*4+1] = o[no][1];
            p[2+no*4+2] = o[no][2]; p[2+no*4+3] = o[no][3];
        }
    }
    __syncthreads();
    if (grp == 0) {
        #pragma unroll
        for (int g2 = 0; g2 < NG-1; g2++) {
            const float* p = mb + (g2*128 + gtid)*MW;
            ls0 += p[0]; ls1 += p[1];
            #pragma unroll
            for (int no = 0; no < NO; no++) {
                o[no][0] += p[2+no*4+0]; o[no][1] += p[2+no*4+1];
                o[no][2] += p[2+no*4+2]; o[no][3] += p[2+no*4+3];
            }
        }
        const float i0 = 1.f / ls0, i1 = 1.f / ls1;
        const int rl = wg*16 + (lane >> 2);      // local row 0..63
        const int c0 = (lane & 3) * 2;
        #pragma unroll
        for (int no = 0; no < NO; no++) {
            *(float2*)&ybuf[rl*DOUT + no*8 + c0] =
                make_float2(o[no][0]*i0, o[no][1]*i0);
            *(float2*)&ybuf[(rl+8)*DOUT + no*8 + c0] =
                make_float2(o[no][2]*i1, o[no][3]*i1);
        }
    }
    __syncthreads();

    // ---- LN phase: all 16 warps, 4 rows each, lane owns 4 cols (float4) ----
    #pragma unroll
    for (int r = 0; r < 4; r++) {
        const int rr = warp*4 + r;               // local row 0..63
        float4 y4 = *(float4*)&ybuf[rr*DOUT + lane*4];
        const float4 p4 = *(const float4*)&projg[base + (size_t)(q0+rr)*DOUT + lane*4];
        y4.x += p4.x; y4.y += p4.y; y4.z += p4.z; y4.w += p4.w;
        float s  = y4.x + y4.y + y4.z + y4.w;
        float s2 = y4.x*y4.x + y4.y*y4.y + y4.z*y4.z + y4.w*y4.w;
        #pragma unroll
        for (int off = 16; off > 0; off >>= 1) {
            s  += __shfl_xor_sync(0xffffffffu, s,  off);
            s2 += __shfl_xor_sync(0xffffffffu, s2, off);
        }
        const float mu = s * (1.f/128.f);
        const float rv = rsqrtf(s2*(1.f/128.f) - mu*mu + 1e-3f);
        const float4 g4 = *(const float4*)&lng[lane*4];
        const float4 b4 = *(const float4*)&lnb[lane*4];
        float4 out4;
        out4.x = (y4.x - mu)*rv*g4.x + b4.x;
        out4.y = (y4.y - mu)*rv*g4.y + b4.y;
        out4.z = (y4.z - mu)*rv*g4.z + b4.z;
        out4.w = (y4.w - mu)*rv*g4.w + b4.w;
        *(float4*)&Og[base + (size_t)(q0+rr)*DOUT + lane*4] = out4;
    }
}

// ---------------- launch -------------------------------------------------------
extern "C" void kernel_launch(void* const* d_in, const int* in_sizes, int n_in,
                              void* d_out, int out_size)
{
    (void)in_sizes; (void)n_in; (void)out_size;
    const float* x   = (const float*)d_in[0];
    // d_in[1] = emb : unused (adjacency mask is a provable no-op)
    const float* q1w = (const float*)d_in[2];
    const float* q1b = (const float*)d_in[3];
    const float* k1w = (const float*)d_in[4];
    const float* k1b = (const float*)d_in[5];
    const float* v1w = (const float*)d_in[6];
    const float* v1b = (const float*)d_in[7];
    const float* q2w = (const float*)d_in[8];
    const float* q2b = (const float*)d_in[9];
    const float* k2w = (const float*)d_in[10];
    const float* k2b = (const float*)d_in[11];
    const float* v2w = (const float*)d_in[12];
    const float* v2b = (const float*)d_in[13];
    const float* pw  = (const float*)d_in[14];
    const float* lng = (const float*)d_in[15];
    const float* lnb = (const float*)d_in[16];
    float* out = (float*)d_out;

    Scratch* sp = nullptr;
    cudaGetSymbolAddress((void**)&sp, g_s);

    const int SMEM_A  = (64*136 + 16*32*136) * 2;            // 156672 B (attn)
    const int SMEM_Q1 = (2*128*72 + 2*64*136) * 2;           //  71680 B
    cudaFuncSetAttribute(attn1_4h,
                         cudaFuncAttributeMaxDynamicSharedMemorySize, SMEM_A);
    cudaFuncSetAttribute(attn2_mma,
                         cudaFuncAttributeMaxDynamicSharedMemorySize, SMEM_A);
    cudaFuncSetAttribute(qkv1_mma,
                         cudaFuncAttributeMaxDynamicSharedMemorySize, SMEM_Q1);

    qkv1_mma<<<dim3(ROWS/128, 4), 256, SMEM_Q1>>>(x, q1w,q1b, k1w,k1b, v1w,v1b,
        pw, sp->q1, sp->k1, sp->v1, sp->proj);

    attn1_4h<<<dim3(Nn/64, Bn), 512, SMEM_A>>>(sp->q1, sp->k1, sp->v1,
        q2w,q2b, k2w,k2b, v2w,v2b, sp->q2, sp->k2, sp->v2);

    attn2_mma<<<dim3(Nn/64, Bn), 512, SMEM_A>>>(sp->q2, sp->k2, sp->v2,
        sp->proj, lng, lnb, out);
}